// round 3
// baseline (speedup 1.0000x reference)
#include <cuda_runtime.h>
#include <math.h>

typedef unsigned long long ull;
#define Tn 96
#define Bn 64
#define RS 66   // smem row stride in floats (2-way-conflict, 8B aligned)

__device__ __forceinline__ ull pk2(float lo, float hi) {
    ull r; asm("mov.b64 %0,{%1,%2};" : "=l"(r) : "f"(lo), "f"(hi)); return r;
}
__device__ __forceinline__ void upk2(ull v, float &a, float &b) {
    asm("mov.b64 {%0,%1},%2;" : "=f"(a), "=f"(b) : "l"(v));
}
__device__ __forceinline__ void ffma2(ull &d, ull a, ull b) {
    asm("fma.rn.f32x2 %0,%1,%2,%0;" : "+l"(d) : "l"(a), "l"(b));
}

// ---------- scratch (device globals; no runtime allocation) ----------
__device__ __align__(256) float g_Pt[4 * 4096];                   // [m][k][n] transposed diffusion ops
__device__ __align__(256) float g_WX[2][5 * 64 * 192];            // x-part weights [m][k][o]
__device__ __align__(256) float g_WgH[2][5 * 64 * 128];           // h-part gate weights
__device__ __align__(256) float g_WcH[2][5 * 64 * 64];            // h-part cand weights
__device__ __align__(256) float g_Gx[(size_t)Tn * Bn * 64 * 128]; // gate x-contribution (+bg)
__device__ __align__(256) float g_Cx[(size_t)Tn * Bn * 64 * 64];  // cand x-contribution (+bc)
__device__ __align__(256) float g_Hseq[(size_t)Tn * Bn * 4096];   // layer-0 outputs
__device__ __align__(256) float g_H[Bn * 4096];
__device__ __align__(256) float g_RH[Bn * 4096];
__device__ __align__(256) float g_U[Bn * 4096];
__device__ __align__(256) float g_Last[Bn * 4096];

// ---------- P matrices: P1=S0, P2=2S0^2-I, P3=S1S0, P4=2S1P3-S0 ----------
__global__ void k_prep(const float* __restrict__ S0, const float* __restrict__ S1) {
    __shared__ float s0[4096], s1[4096];
    int tid = threadIdx.x;
    for (int i = tid; i < 4096; i += 256) { s0[i] = S0[i]; s1[i] = S1[i]; }
    __syncthreads();
    for (int i = tid; i < 4096; i += 256) {
        int n = i >> 6, k = i & 63;
        float a2 = 0.f, a3 = 0.f;
        for (int j = 0; j < 64; j++) {
            a2 += s0[n * 64 + j] * s0[j * 64 + k];
            a3 += s1[n * 64 + j] * s0[j * 64 + k];
        }
        g_Pt[k * 64 + n] = s0[i];
        g_Pt[4096 + k * 64 + n] = 2.f * a2 - (n == k ? 1.f : 0.f);
        g_Pt[2 * 4096 + k * 64 + n] = a3;
    }
    __syncthreads();
    for (int i = tid; i < 4096; i += 256) {
        int n = i >> 6, k = i & 63;
        float a4 = 0.f;
        for (int j = 0; j < 64; j++) a4 += s1[n * 64 + j] * g_Pt[2 * 4096 + k * 64 + j];
        g_Pt[3 * 4096 + k * 64 + n] = 2.f * a4 - s0[i];
    }
}

// ---------- weight repack: original row index = f*5+m, f<64 x-part, f>=64 h-part ----------
__global__ void k_pack(const float* __restrict__ Wg0, const float* __restrict__ Wc0,
                       const float* __restrict__ Wg1, const float* __restrict__ Wc1) {
    const int WXsz = 5 * 64 * 192, WgHsz = 5 * 64 * 128, WcHsz = 5 * 64 * 64;
    const int PER_L = WXsz + WgHsz + WcHsz;
    for (int i = blockIdx.x * blockDim.x + threadIdx.x; i < 2 * PER_L; i += gridDim.x * blockDim.x) {
        int L = i / PER_L, r = i % PER_L;
        const float* Wg = L ? Wg1 : Wg0;
        const float* Wc = L ? Wc1 : Wc0;
        if (r < WXsz) {
            int m = r / (64 * 192), k = (r / 192) % 64, o = r % 192;
            g_WX[L][r] = (o < 128) ? Wg[(k * 5 + m) * 128 + o] : Wc[(k * 5 + m) * 64 + (o - 128)];
        } else if (r < WXsz + WgHsz) {
            int q = r - WXsz, m = q / (64 * 128), k = (q / 128) % 64, o = q % 128;
            g_WgH[L][q] = Wg[((64 + k) * 5 + m) * 128 + o];
        } else {
            int q = r - WXsz - WgHsz, m = q / 4096, k = (q / 64) % 64, o = q % 64;
            g_WcH[L][q] = Wc[((64 + k) * 5 + m) * 64 + o];
        }
    }
}

__global__ void k_zeroH() {
    int i = blockIdx.x * blockDim.x + threadIdx.x;
    if (i < Bn * 4096) g_H[i] = 0.f;
}

// ---------- unified diffconv+GEMM kernel. MODE: 0=PRE(out192), 1=GATE(128), 2=CAND(64) ----------
template <int MODE>
__global__ void k_main(int layer, int tpar, const float* __restrict__ xin,
                       const float* __restrict__ bg, const float* __restrict__ bc,
                       const int* __restrict__ seql) {
    constexpr int OUT = (MODE == 0) ? 192 : (MODE == 1) ? 128 : 64;
    constexpr int CPT = OUT / 8;  // cols per thread
    constexpr int NA = CPT / 2;   // ull accumulators
    extern __shared__ float sm[];
    float* hfull = sm;                // [64][RS]
    float* xsr = sm + 64 * RS;        // [128][RS]  (4 m-slices x 32 rows)
    float* Bs = sm + 192 * RS;        // [64][OUT]  (byte offset 50688, 16B aligned)
    const int tid = threadIdx.x;
    const int ng = blockIdx.x;        // row half
    const int b = blockIdx.z;
    const int t = (MODE == 0) ? blockIdx.y : tpar;

    const float* src;
    if (MODE == 0) src = layer ? (g_Hseq + ((size_t)t * Bn + b) * 4096) : (xin + ((size_t)b * Tn + t) * 4096);
    else if (MODE == 1) src = g_H + b * 4096;
    else src = g_RH + b * 4096;

    for (int i = tid * 2; i < 4096; i += 512) {
        int n = i >> 6, c = i & 63;
        *(float2*)&hfull[n * RS + c] = *(const float2*)&src[i];
    }
    __syncthreads();

    // diffusion for this CTA's 32 rows, all 4 operators (8B smem loads: RS*4 % 16 != 0)
    {
        int rowid = tid >> 1, jh = tid & 1;
        int m = rowid >> 5, nl = rowid & 31, n = ng * 32 + nl;
        ull acc[16];
#pragma unroll
        for (int j = 0; j < 16; j++) acc[j] = 0ull;
        const float* P = g_Pt + m * 4096 + n;
        for (int k = 0; k < 64; k++) {
            float p = __ldg(P + k * 64);
            ull p2 = pk2(p, p);
            const ull* xr = (const ull*)&hfull[k * RS + jh * 32];
#pragma unroll
            for (int j = 0; j < 16; j++) ffma2(acc[j], p2, xr[j]);
        }
        ull* dst = (ull*)&xsr[(m * 32 + nl) * RS + jh * 32];
#pragma unroll
        for (int j = 0; j < 16; j++) dst[j] = acc[j];
    }
    __syncthreads();

    // GEMM: out[n][:] = sum_m sum_k xs[m][n][k] * W[m][k][:]
    const int nl = tid & 31, cg = tid >> 5;
    const int n = ng * 32 + nl;
    ull acc[NA];
#pragma unroll
    for (int j = 0; j < NA; j++) acc[j] = 0ull;
    const float* W = (MODE == 0) ? g_WX[layer] : (MODE == 1) ? g_WgH[layer] : g_WcH[layer];
    for (int m = 0; m < 5; m++) {
        const float4* s4 = (const float4*)(W + m * 64 * OUT);
        float4* d4 = (float4*)Bs;
        for (int i = tid; i < 64 * OUT / 4; i += 256) d4[i] = s4[i];
        __syncthreads();
        const float* A = (m == 0) ? &hfull[n * RS] : &xsr[((m - 1) * 32 + nl) * RS];
        for (int k = 0; k < 64; k++) {
            float a = A[k];
            ull a2 = pk2(a, a);
            const ull* br = (const ull*)&Bs[k * OUT + cg * CPT];
#pragma unroll
            for (int j = 0; j < NA; j++) ffma2(acc[j], a2, br[j]);
        }
        __syncthreads();
    }

    if (MODE == 0) {
        size_t gb = (((size_t)t * Bn + b) * 64 + n) * 128;
        size_t cb = (((size_t)t * Bn + b) * 64 + n) * 64;
#pragma unroll
        for (int j = 0; j < NA; j++) {
            int o = cg * CPT + 2 * j;
            float lo, hi; upk2(acc[j], lo, hi);
            if (o < 128) {
                g_Gx[gb + o] = lo + bg[o];
                g_Gx[gb + o + 1] = hi + bg[o + 1];
            } else {
                g_Cx[cb + o - 128] = lo + bc[o - 128];
                g_Cx[cb + o - 127] = hi + bc[o - 127];
            }
        }
    } else if (MODE == 1) {
        size_t gb = (((size_t)t * Bn + b) * 64 + n) * 128;
        int hb = (b * 64 + n) * 64;
#pragma unroll
        for (int j = 0; j < NA; j++) {
            int o = cg * CPT + 2 * j;
            float lo, hi; upk2(acc[j], lo, hi);
            float s0 = 1.f / (1.f + expf(-(lo + g_Gx[gb + o])));
            float s1 = 1.f / (1.f + expf(-(hi + g_Gx[gb + o + 1])));
            if (o < 64) {
                g_RH[hb + o] = s0 * hfull[n * RS + o];
                g_RH[hb + o + 1] = s1 * hfull[n * RS + o + 1];
            } else {
                g_U[hb + o - 64] = s0;
                g_U[hb + o - 63] = s1;
            }
        }
    } else {
        size_t cb = (((size_t)t * Bn + b) * 64 + n) * 64;
        int hb = (b * 64 + n) * 64;
        bool last = (layer == 1) && (seql[b] - 1 == t);
#pragma unroll
        for (int j = 0; j < NA; j++) {
            int o = cg * CPT + 2 * j;
            float lo, hi; upk2(acc[j], lo, hi);
            float c0 = tanhf(lo + g_Cx[cb + o]);
            float c1 = tanhf(hi + g_Cx[cb + o + 1]);
            float u0 = g_U[hb + o], u1 = g_U[hb + o + 1];
            float h0 = g_H[hb + o], h1 = g_H[hb + o + 1];
            float n0 = u0 * h0 + (1.f - u0) * c0;
            float n1 = u1 * h1 + (1.f - u1) * c1;
            g_H[hb + o] = n0;
            g_H[hb + o + 1] = n1;
            if (layer == 0) {
                g_Hseq[((size_t)t * Bn + b) * 4096 + n * 64 + o] = n0;
                g_Hseq[((size_t)t * Bn + b) * 4096 + n * 64 + o + 1] = n1;
            }
            if (last) {
                g_Last[hb + o] = n0;
                g_Last[hb + o + 1] = n1;
            }
        }
    }
}

// ---------- output head ----------
__global__ void k_head(const float* __restrict__ fcw, const float* __restrict__ fcb,
                       const float* __restrict__ idw, const float* __restrict__ idb,
                       float* __restrict__ out) {
    __shared__ float hb[4096];
    __shared__ float w[64 * 54];
    __shared__ float bias[54];
    int b = blockIdx.x, tid = threadIdx.x;
    for (int i = tid; i < 4096; i += 256) hb[i] = fmaxf(g_Last[b * 4096 + i], 0.f);
    for (int i = tid; i < 64 * 54; i += 256) {
        int k = i / 54, c = i % 54;
        w[i] = (c < 4) ? fcw[k * 4 + c] : idw[k * 50 + c - 4];
    }
    if (tid < 54) bias[tid] = (tid < 4) ? fcb[tid] : idb[tid - 4];
    __syncthreads();
    if (tid < 54) {
        float best = -INFINITY;
        for (int n = 0; n < 64; n++) {
            float s = bias[tid];
            for (int k = 0; k < 64; k++) s += hb[n * 64 + k] * w[k * 54 + tid];
            best = fmaxf(best, s);
        }
        if (tid < 4) out[b * 4 + tid] = best;
        else out[256 + b * 50 + tid - 4] = best;
    }
}

extern "C" void kernel_launch(void* const* d_in, const int* in_sizes, int n_in,
                              void* d_out, int out_size) {
    const float* xseq = (const float*)d_in[0];
    const int* seql = (const int*)d_in[1];
    const float* S0 = (const float*)d_in[2];
    const float* S1 = (const float*)d_in[3];
    const float* Wg0 = (const float*)d_in[4]; const float* bg0 = (const float*)d_in[5];
    const float* Wc0 = (const float*)d_in[6]; const float* bc0 = (const float*)d_in[7];
    const float* Wg1 = (const float*)d_in[8]; const float* bg1 = (const float*)d_in[9];
    const float* Wc1 = (const float*)d_in[10]; const float* bc1 = (const float*)d_in[11];
    const float* fcw = (const float*)d_in[12]; const float* fcb = (const float*)d_in[13];
    const float* idw = (const float*)d_in[14]; const float* idb = (const float*)d_in[15];
    float* out = (float*)d_out;

    const int SM_PRE = 192 * RS * 4 + 64 * 192 * 4;   // 99840
    const int SM_GATE = 192 * RS * 4 + 64 * 128 * 4;  // 83456
    const int SM_CAND = 192 * RS * 4 + 64 * 64 * 4;   // 67072
    cudaFuncSetAttribute(k_main<0>, cudaFuncAttributeMaxDynamicSharedMemorySize, SM_PRE);
    cudaFuncSetAttribute(k_main<1>, cudaFuncAttributeMaxDynamicSharedMemorySize, SM_GATE);
    cudaFuncSetAttribute(k_main<2>, cudaFuncAttributeMaxDynamicSharedMemorySize, SM_CAND);

    k_prep<<<1, 256>>>(S0, S1);
    k_pack<<<240, 256>>>(Wg0, Wc0, Wg1, Wc1);

    for (int L = 0; L < 2; L++) {
        k_main<0><<<dim3(2, Tn, Bn), 256, SM_PRE>>>(L, 0, xseq, L ? bg1 : bg0, L ? bc1 : bc0, seql);
        k_zeroH<<<1024, 256>>>();
        for (int t = 0; t < Tn; t++) {
            k_main<1><<<dim3(2, 1, Bn), 256, SM_GATE>>>(L, t, nullptr, nullptr, nullptr, seql);
            k_main<2><<<dim3(2, 1, Bn), 256, SM_CAND>>>(L, t, nullptr, nullptr, nullptr, seql);
        }
    }
    k_head<<<Bn, 256>>>(fcw, fcb, idw, idb, out);
}